// round 7
// baseline (speedup 1.0000x reference)
#include <cuda_runtime.h>
#include <math.h>

#define B_ 8
#define H_ 256
#define W_ 256
#define C_ 128
#define HW_ (H_ * W_)          // 65536
#define P_ (B_ * HW_)          // 524288 pixels
#define NCHUNK_ 256            // chunks per batch
#define PIX_PER_CHUNK_ (HW_ / NCHUNK_)   // 256
#define THRESH_ 0.8f
#define EPS_ 1e-3f

// ---- scratch (device globals; no allocation allowed) ----
__device__ float g_pooled[P_ * 2];                 // 4 MB
__device__ float g_gmap[P_];                       // 2 MB
__device__ float g_bmap[P_];                       // 2 MB
__device__ unsigned char g_mask[P_];               // 0.5 MB
__device__ int   g_counts[B_];
__device__ int   g_done[B_];
__device__ float4 g_partials[B_ * NCHUNK_ * C_];   // 4 MB
__device__ float g_params[B_ * 2 * C_ * 2];        // 8 KB

// ============================================================
// Kernel 1: channel max/avg pool (forward batch order).
// ============================================================
__global__ void pool_kernel(const float* __restrict__ in) {
    if (blockIdx.x == 0 && threadIdx.x < B_) {
        g_counts[threadIdx.x] = 0;
        g_done[threadIdx.x] = 0;
    }

    int warp = threadIdx.x >> 5, lane = threadIdx.x & 31;
    int pix0 = blockIdx.x * 32 + warp * 4;
    const float4* p = (const float4*)in;

    float4 v[4];
    #pragma unroll
    for (int k = 0; k < 4; k++)
        v[k] = p[(size_t)(pix0 + k) * 32 + lane];

    float mx[4], sm[4];
    #pragma unroll
    for (int k = 0; k < 4; k++) {
        mx[k] = fmaxf(fmaxf(v[k].x, v[k].y), fmaxf(v[k].z, v[k].w));
        sm[k] = (v[k].x + v[k].y) + (v[k].z + v[k].w);
    }
    #pragma unroll
    for (int o = 16; o; o >>= 1) {
        #pragma unroll
        for (int k = 0; k < 4; k++) {
            mx[k] = fmaxf(mx[k], __shfl_xor_sync(0xFFFFFFFFu, mx[k], o));
            sm[k] += __shfl_xor_sync(0xFFFFFFFFu, sm[k], o);
        }
    }
    if (lane == 0) {
        float2* po = ((float2*)g_pooled) + pix0;
        #pragma unroll
        for (int k = 0; k < 4; k++) {
            float2 r; r.x = mx[k]; r.y = sm[k] * (1.0f / (float)C_);
            po[k] = r;
        }
    }
}

// ============================================================
// Kernel 2: FUSED conv pipeline (32x32 tiles, xmap stays in shared).
// ============================================================
__global__ void fused_conv_kernel(const float* __restrict__ w_sr,
                                  const float* __restrict__ b_sr,
                                  const float* __restrict__ w_g,
                                  const float* __restrict__ b_g,
                                  const float* __restrict__ w_b,
                                  const float* __restrict__ b_b) {
    __shared__ float2 sp[36][37];
    __shared__ float  xm[34][35];
    __shared__ float  swsr[18], swg[9], swb[9], sbias[3];
    __shared__ int    scnt[8];

    int t = threadIdx.x;
    int b  = blockIdx.x >> 6;
    int tt = blockIdx.x & 63;
    int th = (tt >> 3) << 5;
    int tw = (tt & 7) << 5;
    int bbase = b << 16;

    if (t < 18) swsr[t] = w_sr[t];
    if (t < 9) { swg[t] = w_g[t]; swb[t] = w_b[t]; }
    if (t == 0) { sbias[0] = b_sr[0]; sbias[1] = b_g[0]; sbias[2] = b_b[0]; }

    const float2* pooled2 = (const float2*)g_pooled;
    for (int l = t; l < 36 * 36; l += 256) {
        int i = l / 36, j = l % 36;
        int h = th - 2 + i, w = tw - 2 + j;
        float2 val = make_float2(0.f, 0.f);
        if (h >= 0 && h < H_ && w >= 0 && w < W_)
            val = pooled2[bbase + (h << 8) + w];
        sp[i][j] = val;
    }
    __syncthreads();

    for (int l = t; l < 34 * 34; l += 256) {
        int i = l / 34, j = l % 34;
        int h = th - 1 + i, w = tw - 1 + j;
        float x = 0.f;
        if (h >= 0 && h < H_ && w >= 0 && w < W_) {
            float acc = sbias[0];
            #pragma unroll
            for (int kh = 0; kh < 3; kh++)
                #pragma unroll
                for (int kw = 0; kw < 3; kw++) {
                    float2 pv = sp[i + kh][j + kw];
                    acc += pv.x * swsr[(kh * 3 + kw) * 2]
                         + pv.y * swsr[(kh * 3 + kw) * 2 + 1];
                }
            x = 1.0f / (1.0f + expf(-acc));
        }
        xm[i][j] = x;
    }
    __syncthreads();

    int cnt = 0;
    #pragma unroll
    for (int it = 0; it < 4; it++) {
        int l = t + it * 256;
        int i = l >> 5, j = l & 31;
        float accg = sbias[1], accb = sbias[2];
        #pragma unroll
        for (int kh = 0; kh < 3; kh++)
            #pragma unroll
            for (int kw = 0; kw < 3; kw++) {
                float xv = xm[i + kh][j + kw];
                accg += xv * swg[kh * 3 + kw];
                accb += xv * swb[kh * 3 + kw];
            }
        float x = xm[i + 1][j + 1];
        int m = (x > THRESH_) ? 1 : 0;
        int pixel = bbase + ((th + i) << 8) + tw + j;
        g_mask[pixel] = (unsigned char)m;
        g_gmap[pixel] = accg;
        g_bmap[pixel] = accb;
        cnt += m;
    }
    #pragma unroll
    for (int o = 16; o; o >>= 1) cnt += __shfl_xor_sync(0xFFFFFFFFu, cnt, o);
    int warp = t >> 5, lane = t & 31;
    if (lane == 0) scnt[warp] = cnt;
    __syncthreads();
    if (t == 0) {
        int s = 0;
        #pragma unroll
        for (int i = 0; i < 8; i++) s += scnt[i];
        atomicAdd(&g_counts[b], s);
    }
}

// ============================================================
// Kernel 3: per-PAIR moments. grid = (NCHUNK_, 2); b = base + blockIdx.y.
// Default-cached reads (retain for the apply stage that follows).
// Last block of each batch finalizes mu/invstd (partials L2-hot).
// ============================================================
__global__ void moments_pair_kernel(const float* __restrict__ in, int base) {
    int chunk = blockIdx.x;
    int b     = base + blockIdx.y;
    int t     = threadIdx.x;
    int c4    = t & 31;
    int sub   = t >> 5;

    __shared__ float smask[PIX_PER_CHUNK_];
    if (t < PIX_PER_CHUNK_ / 4) {
        uchar4 m4 = ((const uchar4*)(g_mask + b * HW_ + chunk * PIX_PER_CHUNK_))[t];
        smask[t * 4 + 0] = (float)m4.x;
        smask[t * 4 + 1] = (float)m4.y;
        smask[t * 4 + 2] = (float)m4.z;
        smask[t * 4 + 3] = (float)m4.w;
    }
    __syncthreads();

    const float4* baseptr = (const float4*)(in + ((size_t)b * HW_ + (size_t)chunk * PIX_PER_CHUNK_) * C_) + c4;

    float4 s1  = make_float4(0,0,0,0), s2  = make_float4(0,0,0,0);
    float4 s1v = make_float4(0,0,0,0), s2v = make_float4(0,0,0,0);

    for (int i0 = sub; i0 < PIX_PER_CHUNK_; i0 += 32) {
        float4 v[4];
        #pragma unroll
        for (int k = 0; k < 4; k++)
            v[k] = baseptr[(size_t)(i0 + 8 * k) * 32];
        #pragma unroll
        for (int k = 0; k < 4; k++) {
            float fm = smask[i0 + 8 * k];
            s1.x += v[k].x;              s1.y += v[k].y;
            s1.z += v[k].z;              s1.w += v[k].w;
            s2.x += v[k].x * v[k].x;     s2.y += v[k].y * v[k].y;
            s2.z += v[k].z * v[k].z;     s2.w += v[k].w * v[k].w;
            s1v.x += v[k].x * fm;        s1v.y += v[k].y * fm;
            s1v.z += v[k].z * fm;        s1v.w += v[k].w * fm;
            s2v.x += v[k].x * v[k].x * fm; s2v.y += v[k].y * v[k].y * fm;
            s2v.z += v[k].z * v[k].z * fm; s2v.w += v[k].w * v[k].w * fm;
        }
    }

    __shared__ float4 r1[256], r2[256], r3[256], r4[256];
    r1[t] = s1v; r2[t] = s2v; r3[t] = s1; r4[t] = s2;
    __syncthreads();

    if (t < C_) {
        int cc4 = t >> 2, k = t & 3;
        float a1 = 0.f, a2 = 0.f, a3 = 0.f, a4 = 0.f;
        #pragma unroll
        for (int s = 0; s < 8; s++) {
            int idx = s * 32 + cc4;
            a1 += ((const float*)&r1[idx])[k];
            a2 += ((const float*)&r2[idx])[k];
            a3 += ((const float*)&r3[idx])[k];
            a4 += ((const float*)&r4[idx])[k];
        }
        g_partials[((size_t)b * NCHUNK_ + chunk) * C_ + t] = make_float4(a1, a2, a3, a4);
    }

    // ---- last block of this batch finalizes ----
    __shared__ int is_last;
    __threadfence();
    __syncthreads();
    if (t == 0) is_last = (atomicAdd(&g_done[b], 1) == NCHUNK_ - 1) ? 1 : 0;
    __syncthreads();
    if (!is_last) return;

    {
        int c    = t & 127;
        int half = t >> 7;
        const float4* pp = g_partials + (size_t)b * NCHUNK_ * C_ + (size_t)(half * (NCHUNK_ / 2)) * C_ + c;
        float a1 = 0.f, a2 = 0.f, a3 = 0.f, a4 = 0.f;
        #pragma unroll 8
        for (int k = 0; k < NCHUNK_ / 2; k++) {
            float4 p = pp[(size_t)k * C_];
            a1 += p.x; a2 += p.y; a3 += p.z; a4 += p.w;
        }
        r1[t] = make_float4(a1, a2, a3, a4);
    }
    __syncthreads();
    if (t < C_) {
        float4 lo = r1[t], hi = r1[t + 128];
        float s1v_ = lo.x + hi.x;
        float s2v_ = lo.y + hi.y;
        float s1_  = lo.z + hi.z;
        float s2_  = lo.w + hi.w;

        float cnt_v = (float)g_counts[b];
        float cnt_m = (float)HW_ - cnt_v;
        float s1m = s1_ - s1v_;
        float s2m = s2_ - s2v_;

        float fs_v  = cnt_v + EPS_;
        float mu_v  = s1v_ / fs_v;
        float var_v = (s2v_ - 2.f * mu_v * s1v_ + mu_v * mu_v * cnt_v) / fs_v;
        float is_v  = 1.0f / sqrtf(var_v + EPS_);
        float fs_m  = cnt_m + EPS_;
        float mu_m  = s1m / fs_m;
        float var_m = (s2m - 2.f * mu_m * s1m + mu_m * mu_m * cnt_m) / fs_m;
        float is_m  = 1.0f / sqrtf(var_m + EPS_);

        ((float2*)g_params)[((size_t)b * 2 + 1) * C_ + t] = make_float2(mu_v, is_v);
        ((float2*)g_params)[((size_t)b * 2 + 0) * C_ + t] = make_float2(mu_m, is_m);
    }
}

// ============================================================
// Kernel 4: per-PAIR apply. Reads input via __ldcs (last use),
// writes output via __stcs (don't pollute L2).
// ============================================================
__global__ void apply_pair_kernel(const float* __restrict__ in,
                                  float* __restrict__ out, int base) {
    int t = threadIdx.x;
    int pix0 = base * HW_ + blockIdx.x * 32;
    size_t base4 = (size_t)pix0 * 32;
    int b = pix0 >> 16;

    __shared__ float4 sparams[128];   // [region(2)][c4(32)][2]
    if (t < 128) sparams[t] = ((const float4*)g_params)[b * 128 + t];
    __syncthreads();

    const float4* in4 = (const float4*)in;
    float4* out4 = (float4*)out;

    float4 v[4];
    #pragma unroll
    for (int k = 0; k < 4; k++)
        v[k] = __ldcs(&in4[base4 + t + 256 * k]);

    #pragma unroll
    for (int k = 0; k < 4; k++) {
        int i4  = t + 256 * k;
        int pix = pix0 + (i4 >> 5);
        int c4  = i4 & 31;
        int m        = g_mask[pix];
        float beta   = g_bmap[pix];
        float gamma  = g_gmap[pix];
        float4 p0 = sparams[m * 64 + c4 * 2];
        float4 p1 = sparams[m * 64 + c4 * 2 + 1];
        float4 o;
        o.x = (v[k].x - p0.x) * p0.y * beta + gamma;
        o.y = (v[k].y - p0.z) * p0.w * beta + gamma;
        o.z = (v[k].z - p1.x) * p1.y * beta + gamma;
        o.w = (v[k].w - p1.z) * p1.w * beta + gamma;
        __stcs(&out4[base4 + i4], o);
    }
}

// ============================================================
extern "C" void kernel_launch(void* const* d_in, const int* in_sizes, int n_in,
                              void* d_out, int out_size) {
    const float* in      = (const float*)d_in[0];
    const float* w_sr    = (const float*)d_in[1];
    const float* b_sr    = (const float*)d_in[2];
    const float* w_gamma = (const float*)d_in[3];
    const float* b_gamma = (const float*)d_in[4];
    const float* w_beta  = (const float*)d_in[5];
    const float* b_beta  = (const float*)d_in[6];
    float* out = (float*)d_out;

    pool_kernel<<<P_ / 32, 256>>>(in);
    fused_conv_kernel<<<B_ * 64, 256>>>(w_sr, b_sr, w_gamma, b_gamma, w_beta, b_beta);

    // Pipelined stages, reverse pair order (pool's tail is L2-hot):
    for (int base = B_ - 2; base >= 0; base -= 2) {
        moments_pair_kernel<<<dim3(NCHUNK_, 2), 256>>>(in, base);
        apply_pair_kernel<<<2 * HW_ / 32, 256>>>(in, out, base);
    }
}

// round 8
// speedup vs baseline: 1.1991x; 1.1991x over previous
#include <cuda_runtime.h>
#include <math.h>

#define B_ 8
#define H_ 256
#define W_ 256
#define C_ 128
#define HW_ (H_ * W_)          // 65536
#define P_ (B_ * HW_)          // 524288 pixels
#define NBLK_ 128              // reduction chunks per batch
#define PIX_PER_CHUNK_ (HW_ / NBLK_)   // 512
#define THRESH_ 0.8f
#define EPS_ 1e-3f

// ---- scratch (device globals; no allocation allowed) ----
__device__ float g_pooled[P_ * 2];                 // 4 MB
__device__ float g_gmap[P_];                       // 2 MB
__device__ float g_bmap[P_];                       // 2 MB
__device__ unsigned char g_mask[P_];               // 0.5 MB
__device__ int   g_counts[B_];
__device__ int   g_done[B_];
__device__ float4 g_partials[B_ * NBLK_ * C_];     // 2 MB
__device__ float g_params[B_ * 2 * C_ * 2];        // 8 KB

// ============================================================
// Kernel 1: channel max/avg pool. 8 pixels per warp (MLP=8).
// Block 0 zeros the per-batch counters.
// ============================================================
__global__ void pool_kernel(const float* __restrict__ in) {
    if (blockIdx.x == 0 && threadIdx.x < B_) {
        g_counts[threadIdx.x] = 0;
        g_done[threadIdx.x] = 0;
    }

    int warp = threadIdx.x >> 5, lane = threadIdx.x & 31;
    int pix0 = blockIdx.x * 64 + warp * 8;
    const float4* p = (const float4*)in;

    float4 v[8];
    #pragma unroll
    for (int k = 0; k < 8; k++)
        v[k] = p[(size_t)(pix0 + k) * 32 + lane];

    float mx[8], sm[8];
    #pragma unroll
    for (int k = 0; k < 8; k++) {
        mx[k] = fmaxf(fmaxf(v[k].x, v[k].y), fmaxf(v[k].z, v[k].w));
        sm[k] = (v[k].x + v[k].y) + (v[k].z + v[k].w);
    }
    #pragma unroll
    for (int o = 16; o; o >>= 1) {
        #pragma unroll
        for (int k = 0; k < 8; k++) {
            mx[k] = fmaxf(mx[k], __shfl_xor_sync(0xFFFFFFFFu, mx[k], o));
            sm[k] += __shfl_xor_sync(0xFFFFFFFFu, sm[k], o);
        }
    }
    float2* po = ((float2*)g_pooled) + pix0;
    #pragma unroll
    for (int k = 0; k < 8; k++) {
        if (lane == k) {
            float2 r; r.x = mx[k]; r.y = sm[k] * (1.0f / (float)C_);
            po[k] = r;
        }
    }
}

// ============================================================
// Kernel 2: FUSED conv pipeline (32x32 tiles, xmap stays in shared).
// ============================================================
__global__ void fused_conv_kernel(const float* __restrict__ w_sr,
                                  const float* __restrict__ b_sr,
                                  const float* __restrict__ w_g,
                                  const float* __restrict__ b_g,
                                  const float* __restrict__ w_b,
                                  const float* __restrict__ b_b) {
    __shared__ float2 sp[36][37];
    __shared__ float  xm[34][35];
    __shared__ float  swsr[18], swg[9], swb[9], sbias[3];
    __shared__ int    scnt[8];

    int t = threadIdx.x;
    int b  = blockIdx.x >> 6;
    int tt = blockIdx.x & 63;
    int th = (tt >> 3) << 5;
    int tw = (tt & 7) << 5;
    int bbase = b << 16;

    if (t < 18) swsr[t] = w_sr[t];
    if (t < 9) { swg[t] = w_g[t]; swb[t] = w_b[t]; }
    if (t == 0) { sbias[0] = b_sr[0]; sbias[1] = b_g[0]; sbias[2] = b_b[0]; }

    const float2* pooled2 = (const float2*)g_pooled;
    for (int l = t; l < 36 * 36; l += 256) {
        int i = l / 36, j = l % 36;
        int h = th - 2 + i, w = tw - 2 + j;
        float2 val = make_float2(0.f, 0.f);
        if (h >= 0 && h < H_ && w >= 0 && w < W_)
            val = pooled2[bbase + (h << 8) + w];
        sp[i][j] = val;
    }
    __syncthreads();

    for (int l = t; l < 34 * 34; l += 256) {
        int i = l / 34, j = l % 34;
        int h = th - 1 + i, w = tw - 1 + j;
        float x = 0.f;
        if (h >= 0 && h < H_ && w >= 0 && w < W_) {
            float acc = sbias[0];
            #pragma unroll
            for (int kh = 0; kh < 3; kh++)
                #pragma unroll
                for (int kw = 0; kw < 3; kw++) {
                    float2 pv = sp[i + kh][j + kw];
                    acc += pv.x * swsr[(kh * 3 + kw) * 2]
                         + pv.y * swsr[(kh * 3 + kw) * 2 + 1];
                }
            x = 1.0f / (1.0f + __expf(-acc));
        }
        xm[i][j] = x;
    }
    __syncthreads();

    int cnt = 0;
    #pragma unroll
    for (int it = 0; it < 4; it++) {
        int l = t + it * 256;
        int i = l >> 5, j = l & 31;
        float accg = sbias[1], accb = sbias[2];
        #pragma unroll
        for (int kh = 0; kh < 3; kh++)
            #pragma unroll
            for (int kw = 0; kw < 3; kw++) {
                float xv = xm[i + kh][j + kw];
                accg += xv * swg[kh * 3 + kw];
                accb += xv * swb[kh * 3 + kw];
            }
        float x = xm[i + 1][j + 1];
        int m = (x > THRESH_) ? 1 : 0;
        int pixel = bbase + ((th + i) << 8) + tw + j;
        g_mask[pixel] = (unsigned char)m;
        g_gmap[pixel] = accg;
        g_bmap[pixel] = accb;
        cnt += m;
    }
    #pragma unroll
    for (int o = 16; o; o >>= 1) cnt += __shfl_xor_sync(0xFFFFFFFFu, cnt, o);
    int warp = t >> 5, lane = t & 31;
    if (lane == 0) scnt[warp] = cnt;
    __syncthreads();
    if (t == 0) {
        int s = 0;
        #pragma unroll
        for (int i = 0; i < 8; i++) s += scnt[i];
        atomicAdd(&g_counts[b], s);
    }
}

// ============================================================
// Kernel 3: masked + total partial sums per (batch, chunk, channel),
// reverse batch order; MLP=8. Last block per batch finalizes params.
// ============================================================
__global__ void moments_kernel(const float* __restrict__ in) {
    int chunk = blockIdx.x;
    int b     = (B_ - 1) - blockIdx.y;   // reverse batch order
    int t     = threadIdx.x;
    int c4    = t & 31;
    int sub   = t >> 5;

    __shared__ float smask[PIX_PER_CHUNK_];
    if (t < 128) {
        uchar4 m4 = ((const uchar4*)(g_mask + b * HW_ + chunk * PIX_PER_CHUNK_))[t];
        smask[t * 4 + 0] = (float)m4.x;
        smask[t * 4 + 1] = (float)m4.y;
        smask[t * 4 + 2] = (float)m4.z;
        smask[t * 4 + 3] = (float)m4.w;
    }
    __syncthreads();

    const float4* base = (const float4*)(in + ((size_t)b * HW_ + (size_t)chunk * PIX_PER_CHUNK_) * C_) + c4;

    float4 s1  = make_float4(0,0,0,0), s2  = make_float4(0,0,0,0);
    float4 s1v = make_float4(0,0,0,0), s2v = make_float4(0,0,0,0);

    for (int i0 = sub; i0 < PIX_PER_CHUNK_; i0 += 64) {
        float4 v[8];
        #pragma unroll
        for (int k = 0; k < 8; k++)
            v[k] = base[(size_t)(i0 + 8 * k) * 32];
        #pragma unroll
        for (int k = 0; k < 8; k++) {
            float fm = smask[i0 + 8 * k];
            s1.x += v[k].x;                s1.y += v[k].y;
            s1.z += v[k].z;                s1.w += v[k].w;
            s2.x += v[k].x * v[k].x;       s2.y += v[k].y * v[k].y;
            s2.z += v[k].z * v[k].z;       s2.w += v[k].w * v[k].w;
            s1v.x += v[k].x * fm;          s1v.y += v[k].y * fm;
            s1v.z += v[k].z * fm;          s1v.w += v[k].w * fm;
            s2v.x += v[k].x * v[k].x * fm; s2v.y += v[k].y * v[k].y * fm;
            s2v.z += v[k].z * v[k].z * fm; s2v.w += v[k].w * v[k].w * fm;
        }
    }

    __shared__ float4 r1[256], r2[256], r3[256], r4[256];
    r1[t] = s1v; r2[t] = s2v; r3[t] = s1; r4[t] = s2;
    __syncthreads();

    if (t < C_) {
        int cc4 = t >> 2, k = t & 3;
        float a1 = 0.f, a2 = 0.f, a3 = 0.f, a4 = 0.f;
        #pragma unroll
        for (int s = 0; s < 8; s++) {
            int idx = s * 32 + cc4;
            a1 += ((const float*)&r1[idx])[k];
            a2 += ((const float*)&r2[idx])[k];
            a3 += ((const float*)&r3[idx])[k];
            a4 += ((const float*)&r4[idx])[k];
        }
        g_partials[((size_t)b * NBLK_ + chunk) * C_ + t] = make_float4(a1, a2, a3, a4);
    }

    // ---- last block of this batch finalizes ----
    __shared__ int is_last;
    __threadfence();
    __syncthreads();
    if (t == 0) is_last = (atomicAdd(&g_done[b], 1) == NBLK_ - 1) ? 1 : 0;
    __syncthreads();
    if (!is_last) return;

    {
        int c    = t & 127;
        int half = t >> 7;
        const float4* pp = g_partials + (size_t)b * NBLK_ * C_ + (size_t)(half * 64) * C_ + c;
        float a1 = 0.f, a2 = 0.f, a3 = 0.f, a4 = 0.f;
        #pragma unroll 8
        for (int k = 0; k < 64; k++) {
            float4 p = pp[(size_t)k * C_];
            a1 += p.x; a2 += p.y; a3 += p.z; a4 += p.w;
        }
        r1[t] = make_float4(a1, a2, a3, a4);
    }
    __syncthreads();
    if (t < C_) {
        float4 lo = r1[t], hi = r1[t + 128];
        float s1v_ = lo.x + hi.x;
        float s2v_ = lo.y + hi.y;
        float s1_  = lo.z + hi.z;
        float s2_  = lo.w + hi.w;

        float cnt_v = (float)g_counts[b];
        float cnt_m = (float)HW_ - cnt_v;
        float s1m = s1_ - s1v_;
        float s2m = s2_ - s2v_;

        float fs_v  = cnt_v + EPS_;
        float mu_v  = s1v_ / fs_v;
        float var_v = (s2v_ - 2.f * mu_v * s1v_ + mu_v * mu_v * cnt_v) / fs_v;
        float is_v  = 1.0f / sqrtf(var_v + EPS_);
        float fs_m  = cnt_m + EPS_;
        float mu_m  = s1m / fs_m;
        float var_m = (s2m - 2.f * mu_m * s1m + mu_m * mu_m * cnt_m) / fs_m;
        float is_m  = 1.0f / sqrtf(var_m + EPS_);

        ((float2*)g_params)[((size_t)b * 2 + 1) * C_ + t] = make_float2(mu_v, is_v);
        ((float2*)g_params)[((size_t)b * 2 + 0) * C_ + t] = make_float2(mu_m, is_m);
    }
}

// ============================================================
// Kernel 4: out = (x - mu_r) * istd_r * beta + gamma   (R4-identical)
// ============================================================
__global__ void apply_kernel(const float* __restrict__ in, float* __restrict__ out) {
    int t = threadIdx.x;
    size_t base = (size_t)blockIdx.x * 1024;
    int pix0 = blockIdx.x * 32;
    int b = pix0 >> 16;

    __shared__ float4 sparams[128];   // [region(2)][c4(32)][2]
    if (t < 128) sparams[t] = ((const float4*)g_params)[b * 128 + t];
    __syncthreads();

    const float4* in4 = (const float4*)in;
    float4* out4 = (float4*)out;

    float4 v[4];
    #pragma unroll
    for (int k = 0; k < 4; k++)
        v[k] = in4[base + t + 256 * k];

    #pragma unroll
    for (int k = 0; k < 4; k++) {
        int i4  = t + 256 * k;
        int pix = pix0 + (i4 >> 5);
        int c4  = i4 & 31;
        int m        = g_mask[pix];
        float beta   = g_bmap[pix];
        float gamma  = g_gmap[pix];
        float4 p0 = sparams[m * 64 + c4 * 2];
        float4 p1 = sparams[m * 64 + c4 * 2 + 1];
        float4 o;
        o.x = (v[k].x - p0.x) * p0.y * beta + gamma;
        o.y = (v[k].y - p0.z) * p0.w * beta + gamma;
        o.z = (v[k].z - p1.x) * p1.y * beta + gamma;
        o.w = (v[k].w - p1.z) * p1.w * beta + gamma;
        out4[base + i4] = o;
    }
}

// ============================================================
extern "C" void kernel_launch(void* const* d_in, const int* in_sizes, int n_in,
                              void* d_out, int out_size) {
    const float* in      = (const float*)d_in[0];
    const float* w_sr    = (const float*)d_in[1];
    const float* b_sr    = (const float*)d_in[2];
    const float* w_gamma = (const float*)d_in[3];
    const float* b_gamma = (const float*)d_in[4];
    const float* w_beta  = (const float*)d_in[5];
    const float* b_beta  = (const float*)d_in[6];
    float* out = (float*)d_out;

    pool_kernel<<<P_ / 64, 256>>>(in);
    fused_conv_kernel<<<B_ * 64, 256>>>(w_sr, b_sr, w_gamma, b_gamma, w_beta, b_beta);
    moments_kernel<<<dim3(NBLK_, B_), 256>>>(in);
    apply_kernel<<<P_ / 32, 256>>>(in, out);
}